// round 2
// baseline (speedup 1.0000x reference)
#include <cuda_runtime.h>
#include <cuda_bf16.h>
#include <mma.h>

using namespace nvcuda;

#define NN 8192
#define DD 64
#define GG 2048

// Scratch: scores/probabilities matrix (256 MB) + row norms.
__device__ float g_S[(size_t)NN * NN];
__device__ float g_norm[NN];

// ---------------------------------------------------------------------------
// K1: row squared norms of encoding
// ---------------------------------------------------------------------------
__global__ void norms_kernel(const float* __restrict__ enc) {
    int i = blockIdx.x * blockDim.x + threadIdx.x;
    if (i >= NN) return;
    const float4* p = (const float4*)(enc + (size_t)i * DD);
    float s = 0.f;
#pragma unroll
    for (int k = 0; k < DD / 4; k++) {
        float4 v = p[k];
        s += v.x * v.x + v.y * v.y + v.z * v.z + v.w * v.w;
    }
    g_norm[i] = s;
}

// ---------------------------------------------------------------------------
// K2: scores S[i,j] = q[j] - sqrt(max(n_i + n_j - 2*dot(e_i,e_j), 0))
// fp32 SIMT tiled GEMM-like; 128x128 block tile, 8x8 per thread, K=64 in 2x32.
// ---------------------------------------------------------------------------
__global__ void scores_kernel(const float* __restrict__ enc,
                              const float* __restrict__ qual) {
    __shared__ float As[32][129];
    __shared__ float Bs[32][129];
    const int i0 = blockIdx.y * 128;
    const int j0 = blockIdx.x * 128;
    const int tid = threadIdx.x;               // 256 threads
    const int tx = tid % 16, ty = tid / 16;    // 16x16 thread grid

    float acc[8][8];
#pragma unroll
    for (int u = 0; u < 8; u++)
#pragma unroll
        for (int v = 0; v < 8; v++) acc[u][v] = 0.f;

    for (int kt = 0; kt < DD; kt += 32) {
        // Transposed loads into smem: As[k][m], Bs[k][n]
        int r = tid / 8;
        int c = (tid % 8) * 4;
#pragma unroll
        for (int rr = 0; rr < 4; rr++) {
            int row = r + rr * 32;
            float4 v = *(const float4*)(enc + (size_t)(i0 + row) * DD + kt + c);
            As[c + 0][row] = v.x; As[c + 1][row] = v.y;
            As[c + 2][row] = v.z; As[c + 3][row] = v.w;
            float4 w = *(const float4*)(enc + (size_t)(j0 + row) * DD + kt + c);
            Bs[c + 0][row] = w.x; Bs[c + 1][row] = w.y;
            Bs[c + 2][row] = w.z; Bs[c + 3][row] = w.w;
        }
        __syncthreads();
#pragma unroll
        for (int k = 0; k < 32; k++) {
            float a[8], b[8];
#pragma unroll
            for (int u = 0; u < 8; u++) a[u] = As[k][ty * 8 + u];
#pragma unroll
            for (int u = 0; u < 8; u++) b[u] = Bs[k][tx * 8 + u];
#pragma unroll
            for (int u = 0; u < 8; u++)
#pragma unroll
                for (int v = 0; v < 8; v++) acc[u][v] += a[u] * b[v];
        }
        __syncthreads();
    }

#pragma unroll
    for (int u = 0; u < 8; u++) {
        int i = i0 + ty * 8 + u;
        float ni = g_norm[i];
        float* Srow = g_S + (size_t)i * NN;
#pragma unroll
        for (int v = 0; v < 8; v++) {
            int j = j0 + tx * 8 + v;
            float d2 = ni + g_norm[j] - 2.f * acc[u][v];
            Srow[j] = qual[j] - sqrtf(fmaxf(d2, 0.f));
        }
    }
}

// ---------------------------------------------------------------------------
// K3: in-place row softmax. One block (256 threads) per row; 32 vals/thread
// held in registers so the row is read once and written once.
// ---------------------------------------------------------------------------
__global__ void softmax_kernel() {
    const int row = blockIdx.x;
    const int tid = threadIdx.x;
    float* S = g_S + (size_t)row * NN;

    float vals[32];
    float m = -1e30f;
#pragma unroll
    for (int k = 0; k < 32; k++) {
        vals[k] = S[tid + k * 256];
        m = fmaxf(m, vals[k]);
    }

    __shared__ float red[8];
#pragma unroll
    for (int off = 16; off; off >>= 1) m = fmaxf(m, __shfl_xor_sync(~0u, m, off));
    if ((tid & 31) == 0) red[tid >> 5] = m;
    __syncthreads();
    if (tid < 8) {
        float x = red[tid];
#pragma unroll
        for (int off = 4; off; off >>= 1) x = fmaxf(x, __shfl_xor_sync(0xffu, x, off));
        if (tid == 0) red[0] = x;
    }
    __syncthreads();
    m = red[0];

    float s = 0.f;
#pragma unroll
    for (int k = 0; k < 32; k++) {
        vals[k] = __expf(vals[k] - m);
        s += vals[k];
    }
    __syncthreads();  // red[0] consumed by all before reuse
#pragma unroll
    for (int off = 16; off; off >>= 1) s += __shfl_xor_sync(~0u, s, off);
    if ((tid & 31) == 0) red[tid >> 5] = s;
    __syncthreads();
    if (tid < 8) {
        float x = red[tid];
#pragma unroll
        for (int off = 4; off; off >>= 1) x += __shfl_xor_sync(0xffu, x, off);
        if (tid == 0) red[0] = x;
    }
    __syncthreads();
    float inv = 1.f / red[0];
#pragma unroll
    for (int k = 0; k < 32; k++) S[tid + k * 256] = vals[k] * inv;
}

// ---------------------------------------------------------------------------
// K4: out = P @ X via tf32 wmma. Block tile 128x128, K-chunk 32,
// 8 warps in a 2(M) x 4(N) grid; each warp 64x32 = 4x2 m16n16k8 fragments.
// ---------------------------------------------------------------------------
__global__ void gemm_kernel(const float* __restrict__ X, float* __restrict__ out) {
    __shared__ float As[128][40];  // 128 x 32 (+8 pad)
    __shared__ float Bs[32][136];  // 32 x 128 (+8 pad)
    const int tid = threadIdx.x;
    const int warp = tid >> 5;
    const int warp_m = warp >> 2;  // 0..1
    const int warp_n = warp & 3;   // 0..3
    const int m0 = blockIdx.y * 128;
    const int n0 = blockIdx.x * 128;

    wmma::fragment<wmma::accumulator, 16, 16, 8, float> c[4][2];
#pragma unroll
    for (int i = 0; i < 4; i++)
#pragma unroll
        for (int j = 0; j < 2; j++) wmma::fill_fragment(c[i][j], 0.f);

    for (int k0 = 0; k0 < NN; k0 += 32) {
        // A: P rows m0..m0+127, cols k0..k0+31 (row-major in smem)
        int r = tid / 8, cc = (tid % 8) * 4;
#pragma unroll
        for (int rr = 0; rr < 4; rr++) {
            int row = r + rr * 32;
            float4 v = *(const float4*)(g_S + (size_t)(m0 + row) * NN + k0 + cc);
            *(float4*)&As[row][cc] = v;
        }
        // B: X rows k0..k0+31, cols n0..n0+127
        int br = tid / 32, bc = (tid % 32) * 4;
#pragma unroll
        for (int rr = 0; rr < 4; rr++) {
            int row = br + rr * 8;
            float4 v = *(const float4*)(X + (size_t)(k0 + row) * GG + n0 + bc);
            *(float4*)&Bs[row][bc] = v;
        }
        __syncthreads();

#pragma unroll
        for (int ks = 0; ks < 32; ks += 8) {
            wmma::fragment<wmma::matrix_a, 16, 16, 8, wmma::precision::tf32, wmma::row_major> a[4];
            wmma::fragment<wmma::matrix_b, 16, 16, 8, wmma::precision::tf32, wmma::row_major> b[2];
#pragma unroll
            for (int i = 0; i < 4; i++) {
                wmma::load_matrix_sync(a[i], &As[warp_m * 64 + i * 16][ks], 40);
#pragma unroll
                for (int t = 0; t < a[i].num_elements; t++)
                    a[i].x[t] = wmma::__float_to_tf32(a[i].x[t]);
            }
#pragma unroll
            for (int j = 0; j < 2; j++) {
                wmma::load_matrix_sync(b[j], &Bs[ks][warp_n * 32 + j * 16], 136);
#pragma unroll
                for (int t = 0; t < b[j].num_elements; t++)
                    b[j].x[t] = wmma::__float_to_tf32(b[j].x[t]);
            }
#pragma unroll
            for (int i = 0; i < 4; i++)
#pragma unroll
                for (int j = 0; j < 2; j++)
                    wmma::mma_sync(c[i][j], a[i], b[j], c[i][j]);
        }
        __syncthreads();
    }

#pragma unroll
    for (int i = 0; i < 4; i++)
#pragma unroll
        for (int j = 0; j < 2; j++)
            wmma::store_matrix_sync(
                out + (size_t)(m0 + warp_m * 64 + i * 16) * GG + n0 + warp_n * 32 + j * 16,
                c[i][j], GG, wmma::mem_row_major);
}

// ---------------------------------------------------------------------------
extern "C" void kernel_launch(void* const* d_in, const int* in_sizes, int n_in,
                              void* d_out, int out_size) {
    // Identify inputs by element count (robust to ordering).
    const float* expr = nullptr;  // N*G
    const float* enc = nullptr;   // N*D
    const float* qual = nullptr;  // N
    for (int i = 0; i < n_in; i++) {
        if (in_sizes[i] == NN * GG) expr = (const float*)d_in[i];
        else if (in_sizes[i] == NN * DD) enc = (const float*)d_in[i];
        else if (in_sizes[i] == NN) qual = (const float*)d_in[i];
    }
    float* out = (float*)d_out;

    norms_kernel<<<NN / 256, 256>>>(enc);
    dim3 g2(NN / 128, NN / 128);
    scores_kernel<<<g2, 256>>>(enc, qual);
    softmax_kernel<<<NN, 256>>>();
    dim3 g4(GG / 128, NN / 128);
    gemm_kernel<<<g4, 256>>>(expr, out);
}

// round 4
// speedup vs baseline: 4.0976x; 4.0976x over previous
#include <cuda_runtime.h>
#include <cuda_fp16.h>
#include <mma.h>
#include <cstdint>

using namespace nvcuda;

#define NN 8192
#define DD 64
#define GG 2048

// Scratch: fp32 scores (256 MB), half probabilities (128 MB), half X (32 MB).
__device__ float g_S[(size_t)NN * NN];
__device__ __half g_Ph[(size_t)NN * NN];
__device__ __half g_Xh[(size_t)NN * GG];
__device__ float g_norm[NN];

// ---------------------------------------------------------------------------
// cp.async helpers
// ---------------------------------------------------------------------------
__device__ __forceinline__ uint32_t smem_u32(const void* p) {
    uint32_t a;
    asm("{ .reg .u64 t; cvta.to.shared.u64 t, %1; cvt.u32.u64 %0, t; }" : "=r"(a) : "l"(p));
    return a;
}
__device__ __forceinline__ void cp_async16(uint32_t s, const void* g) {
    asm volatile("cp.async.cg.shared.global [%0], [%1], 16;" :: "r"(s), "l"(g));
}
__device__ __forceinline__ void cp_commit() {
    asm volatile("cp.async.commit_group;");
}
template <int N>
__device__ __forceinline__ void cp_wait() {
    asm volatile("cp.async.wait_group %0;" :: "n"(N));
}

// ---------------------------------------------------------------------------
// K1: row squared norms of encoding
// ---------------------------------------------------------------------------
__global__ void norms_kernel(const float* __restrict__ enc) {
    int i = blockIdx.x * blockDim.x + threadIdx.x;
    if (i >= NN) return;
    const float4* p = (const float4*)(enc + (size_t)i * DD);
    float s = 0.f;
#pragma unroll
    for (int k = 0; k < DD / 4; k++) {
        float4 v = p[k];
        s += v.x * v.x + v.y * v.y + v.z * v.z + v.w * v.w;
    }
    g_norm[i] = s;
}

// ---------------------------------------------------------------------------
// K2: scores S[i,j] = q[j] - sqrt(max(n_i + n_j - 2*dot(e_i,e_j), 0))
// fp32 SIMT; 128x128 tile, 8x8 per thread.
// ---------------------------------------------------------------------------
__global__ void scores_kernel(const float* __restrict__ enc,
                              const float* __restrict__ qual) {
    __shared__ float As[32][129];
    __shared__ float Bs[32][129];
    const int i0 = blockIdx.y * 128;
    const int j0 = blockIdx.x * 128;
    const int tid = threadIdx.x;
    const int tx = tid % 16, ty = tid / 16;

    float acc[8][8];
#pragma unroll
    for (int u = 0; u < 8; u++)
#pragma unroll
        for (int v = 0; v < 8; v++) acc[u][v] = 0.f;

    for (int kt = 0; kt < DD; kt += 32) {
        int r = tid / 8;
        int c = (tid % 8) * 4;
#pragma unroll
        for (int rr = 0; rr < 4; rr++) {
            int row = r + rr * 32;
            float4 v = *(const float4*)(enc + (size_t)(i0 + row) * DD + kt + c);
            As[c + 0][row] = v.x; As[c + 1][row] = v.y;
            As[c + 2][row] = v.z; As[c + 3][row] = v.w;
            float4 w = *(const float4*)(enc + (size_t)(j0 + row) * DD + kt + c);
            Bs[c + 0][row] = w.x; Bs[c + 1][row] = w.y;
            Bs[c + 2][row] = w.z; Bs[c + 3][row] = w.w;
        }
        __syncthreads();
#pragma unroll
        for (int k = 0; k < 32; k++) {
            float a[8], b[8];
#pragma unroll
            for (int u = 0; u < 8; u++) a[u] = As[k][ty * 8 + u];
#pragma unroll
            for (int u = 0; u < 8; u++) b[u] = Bs[k][tx * 8 + u];
#pragma unroll
            for (int u = 0; u < 8; u++)
#pragma unroll
                for (int v = 0; v < 8; v++) acc[u][v] += a[u] * b[v];
        }
        __syncthreads();
    }

#pragma unroll
    for (int u = 0; u < 8; u++) {
        int i = i0 + ty * 8 + u;
        float ni = g_norm[i];
        float* Srow = g_S + (size_t)i * NN;
#pragma unroll
        for (int v = 0; v < 8; v++) {
            int j = j0 + tx * 8 + v;
            float d2 = ni + g_norm[j] - 2.f * acc[u][v];
            Srow[j] = qual[j] - sqrtf(fmaxf(d2, 0.f));
        }
    }
}

// ---------------------------------------------------------------------------
// K3: row softmax, fp32 in -> half out (g_Ph)
// ---------------------------------------------------------------------------
__global__ void softmax_kernel() {
    const int row = blockIdx.x;
    const int tid = threadIdx.x;
    const float* S = g_S + (size_t)row * NN;
    __half* P = g_Ph + (size_t)row * NN;

    float vals[32];
    float m = -1e30f;
#pragma unroll
    for (int k = 0; k < 32; k++) {
        vals[k] = S[tid + k * 256];
        m = fmaxf(m, vals[k]);
    }

    __shared__ float red[8];
#pragma unroll
    for (int off = 16; off; off >>= 1) m = fmaxf(m, __shfl_xor_sync(~0u, m, off));
    if ((tid & 31) == 0) red[tid >> 5] = m;
    __syncthreads();
    if (tid < 8) {
        float x = red[tid];
#pragma unroll
        for (int off = 4; off; off >>= 1) x = fmaxf(x, __shfl_xor_sync(0xffu, x, off));
        if (tid == 0) red[0] = x;
    }
    __syncthreads();
    m = red[0];

    float s = 0.f;
#pragma unroll
    for (int k = 0; k < 32; k++) {
        vals[k] = __expf(vals[k] - m);
        s += vals[k];
    }
    __syncthreads();
#pragma unroll
    for (int off = 16; off; off >>= 1) s += __shfl_xor_sync(~0u, s, off);
    if ((tid & 31) == 0) red[tid >> 5] = s;
    __syncthreads();
    if (tid < 8) {
        float x = red[tid];
#pragma unroll
        for (int off = 4; off; off >>= 1) x += __shfl_xor_sync(0xffu, x, off);
        if (tid == 0) red[0] = x;
    }
    __syncthreads();
    float inv = 1.f / red[0];
#pragma unroll
    for (int k = 0; k < 32; k++) P[tid + k * 256] = __float2half_rn(vals[k] * inv);
}

// ---------------------------------------------------------------------------
// K3b: convert X (f32, row-major [K, G]) -> half
// ---------------------------------------------------------------------------
__global__ void convx_kernel(const float* __restrict__ X) {
    size_t idx = ((size_t)blockIdx.x * blockDim.x + threadIdx.x) * 4;
    float4 v = *(const float4*)(X + idx);
    __half2* dst = (__half2*)(g_Xh + idx);
    dst[0] = __floats2half2_rn(v.x, v.y);
    dst[1] = __floats2half2_rn(v.z, v.w);
}

// ---------------------------------------------------------------------------
// K4: out = P @ X via fp16 wmma, 3-stage cp.async pipeline.
// Tile 128x128, BK=32, 8 warps (2x4), each warp 64x32 = 4x2 m16n16k16 frags.
// ---------------------------------------------------------------------------
#define BM 128
#define BN 128
#define BK 32
#define NSTG 3
#define A_LDM 72                         // halves: 32 data + 40 pad -> 144B rows
#define B_LDM 136                        // halves: 128 data + 8 pad -> 272B rows
#define A_STG_BYTES (BM * A_LDM * 2)     // 18432
#define B_STG_BYTES (BK * B_LDM * 2)     // 8704
#define STG_BYTES (A_STG_BYTES + B_STG_BYTES)
#define SMEM_GEMM (NSTG * STG_BYTES)     // 81408
#define NCHUNK (NN / BK)                 // 256

__device__ __forceinline__ void load_chunk(uint32_t sA, uint32_t sB,
                                           const __half* gP, const __half* gX,
                                           int m0, int n0, int c, int tid) {
    const size_t k0 = (size_t)c * BK;
    // A: 128 rows x 32 halves (64B/row) = 512 16B chunks
#pragma unroll
    for (int h = 0; h < 2; h++) {
        int ch = tid + h * 256;
        int row = ch >> 2;
        int col16 = ch & 3;
        cp_async16(sA + row * (A_LDM * 2) + col16 * 16,
                   gP + (size_t)(m0 + row) * NN + k0 + col16 * 8);
    }
    // B: 32 rows x 128 halves (256B/row) = 512 16B chunks
#pragma unroll
    for (int h = 0; h < 2; h++) {
        int ch = tid + h * 256;
        int row = ch >> 4;
        int col16 = ch & 15;
        cp_async16(sB + row * (B_LDM * 2) + col16 * 16,
                   gX + (size_t)(k0 + row) * GG + n0 + col16 * 8);
    }
    cp_commit();
}

__global__ void __launch_bounds__(256, 2) gemm_kernel(float* __restrict__ out) {
    extern __shared__ __align__(16) char smem[];
    const uint32_t sbase = smem_u32(smem);
    const int tid = threadIdx.x;
    const int warp = tid >> 5;
    const int warp_m = warp >> 2;   // 0..1
    const int warp_n = warp & 3;    // 0..3
    const int m0 = blockIdx.y * BM;
    const int n0 = blockIdx.x * BN;

    wmma::fragment<wmma::accumulator, 16, 16, 16, float> cfr[4][2];
#pragma unroll
    for (int i = 0; i < 4; i++)
#pragma unroll
        for (int j = 0; j < 2; j++) wmma::fill_fragment(cfr[i][j], 0.f);

    // Prologue: fill stages 0..NSTG-2
#pragma unroll
    for (int c = 0; c < NSTG - 1; c++)
        load_chunk(sbase + c * STG_BYTES, sbase + c * STG_BYTES + A_STG_BYTES,
                   g_Ph, g_Xh, m0, n0, c, tid);

    for (int c = 0; c < NCHUNK; c++) {
        const int st = c % NSTG;
        const __half* Ah = (const __half*)(smem + st * STG_BYTES);
        const __half* Bh = (const __half*)(smem + st * STG_BYTES + A_STG_BYTES);

        if (c + 1 < NCHUNK) cp_wait<NSTG - 2>(); else cp_wait<0>();
        __syncthreads();

#pragma unroll
        for (int ks = 0; ks < BK; ks += 16) {
            wmma::fragment<wmma::matrix_a, 16, 16, 16, __half, wmma::row_major> a[4];
            wmma::fragment<wmma::matrix_b, 16, 16, 16, __half, wmma::row_major> b[2];
#pragma unroll
            for (int i = 0; i < 4; i++)
                wmma::load_matrix_sync(a[i], Ah + (warp_m * 64 + i * 16) * A_LDM + ks, A_LDM);
#pragma unroll
            for (int j = 0; j < 2; j++)
                wmma::load_matrix_sync(b[j], Bh + ks * B_LDM + warp_n * 32 + j * 16, B_LDM);
#pragma unroll
            for (int i = 0; i < 4; i++)
#pragma unroll
                for (int j = 0; j < 2; j++)
                    wmma::mma_sync(cfr[i][j], a[i], b[j], cfr[i][j]);
        }
        __syncthreads();

        if (c + NSTG - 1 < NCHUNK) {
            const int ns = (c + NSTG - 1) % NSTG;
            load_chunk(sbase + ns * STG_BYTES, sbase + ns * STG_BYTES + A_STG_BYTES,
                       g_Ph, g_Xh, m0, n0, c + NSTG - 1, tid);
        }
    }

#pragma unroll
    for (int i = 0; i < 4; i++)
#pragma unroll
        for (int j = 0; j < 2; j++)
            wmma::store_matrix_sync(
                out + (size_t)(m0 + warp_m * 64 + i * 16) * GG + n0 + warp_n * 32 + j * 16,
                cfr[i][j], GG, wmma::mem_row_major);
}

// ---------------------------------------------------------------------------
extern "C" void kernel_launch(void* const* d_in, const int* in_sizes, int n_in,
                              void* d_out, int out_size) {
    const float* expr = nullptr;  // N*G
    const float* enc = nullptr;   // N*D
    const float* qual = nullptr;  // N
    for (int i = 0; i < n_in; i++) {
        if (in_sizes[i] == NN * GG) expr = (const float*)d_in[i];
        else if (in_sizes[i] == NN * DD) enc = (const float*)d_in[i];
        else if (in_sizes[i] == NN) qual = (const float*)d_in[i];
    }
    float* out = (float*)d_out;

    cudaFuncSetAttribute(gemm_kernel, cudaFuncAttributeMaxDynamicSharedMemorySize,
                         SMEM_GEMM);

    norms_kernel<<<NN / 256, 256>>>(enc);
    dim3 g2(NN / 128, NN / 128);
    scores_kernel<<<g2, 256>>>(enc, qual);
    softmax_kernel<<<NN, 256>>>();
    convx_kernel<<<(NN * GG) / (256 * 4), 256>>>(expr);
    dim3 g4(GG / BN, NN / BM);
    gemm_kernel<<<g4, 256, SMEM_GEMM>>>(out);
}